// round 1
// baseline (speedup 1.0000x reference)
#include <cuda_runtime.h>

#define NN   50000
#define NE   800000
#define FIN  128
#define FHID 128
#define FOUT 64

// ---------------- scratch (static __device__ -- no allocations) ----------------
static __device__ int   g_deg[NN];
static __device__ int   g_cur[NN];
static __device__ float g_dinv[NN];
static __device__ int   g_rowptr[NN + 1];
static __device__ int   g_col[NE];
static __device__ float g_h1[(size_t)NN * FHID];   // dinv-scaled x@W1
static __device__ float g_h2[(size_t)NN * FHID];   // relu(layer1 out)
static __device__ float g_h2p[(size_t)NN * FOUT];  // dinv-scaled h2@W2

// ---------------- CSR build ----------------
__global__ void k_init() {
    int i = blockIdx.x * blockDim.x + threadIdx.x;
    if (i < NN) { g_deg[i] = 1; g_cur[i] = 0; }   // deg starts at 1 (self-loop)
}

__global__ void k_count(const int* __restrict__ ei) {
    int e = blockIdx.x * blockDim.x + threadIdx.x;
    if (e < NE) atomicAdd(&g_deg[ei[NE + e]], 1);  // dst = row 1 of edge_index
}

// single-block scan: dinv = rsqrt(deg); rowptr = exclusive scan of (deg-1)
__global__ void k_scan() {
    __shared__ int warp_sums[32];
    __shared__ int chunk_off;
    if (threadIdx.x == 0) chunk_off = 0;
    __syncthreads();
    int lane = threadIdx.x & 31;
    int wid  = threadIdx.x >> 5;
    for (int base = 0; base < NN; base += 1024) {
        int i = base + (int)threadIdx.x;
        int d = (i < NN) ? g_deg[i] : 1;
        if (i < NN) g_dinv[i] = rsqrtf((float)d);
        int v = (i < NN) ? (d - 1) : 0;            // real in-edges only
        int x = v;
        #pragma unroll
        for (int o = 1; o < 32; o <<= 1) {
            int t = __shfl_up_sync(0xFFFFFFFFu, x, o);
            if (lane >= o) x += t;
        }
        if (lane == 31) warp_sums[wid] = x;
        __syncthreads();
        if (wid == 0) {
            int s = warp_sums[lane];
            #pragma unroll
            for (int o = 1; o < 32; o <<= 1) {
                int t = __shfl_up_sync(0xFFFFFFFFu, s, o);
                if (lane >= o) s += t;
            }
            warp_sums[lane] = s;
        }
        __syncthreads();
        int excl = x - v + (wid > 0 ? warp_sums[wid - 1] : 0) + chunk_off;
        if (i < NN) g_rowptr[i] = excl;
        __syncthreads();
        if (threadIdx.x == 1023) chunk_off += warp_sums[31];
        __syncthreads();
    }
    if (threadIdx.x == 0) g_rowptr[NN] = chunk_off;
}

__global__ void k_fill(const int* __restrict__ ei) {
    int e = blockIdx.x * blockDim.x + threadIdx.x;
    if (e < NE) {
        int d = ei[NE + e];
        int p = atomicAdd(&g_cur[d], 1);
        g_col[g_rowptr[d] + p] = ei[e];            // src = row 0
    }
}

// ---------------- GEMM 1: g_h1[i] = dinv[i] * (x @ W1)[i]  (128x128) ----------------
__global__ void __launch_bounds__(256) k_gemm1(const float* __restrict__ X,
                                               const float* __restrict__ W) {
    __shared__ float Xs[64][33];
    __shared__ float Ws[32][128];
    int tx = threadIdx.x;            // 0..31 -> 4 cols (float4)
    int ty = threadIdx.y;            // 0..7  -> 8 rows
    int tid = ty * 32 + tx;
    int row0 = blockIdx.x * 64;
    float4 acc[8];
    #pragma unroll
    for (int r = 0; r < 8; r++) acc[r] = make_float4(0.f, 0.f, 0.f, 0.f);

    for (int k0 = 0; k0 < FIN; k0 += 32) {
        #pragma unroll
        for (int t = tid; t < 64 * 32; t += 256) {
            int r = t >> 5, c = t & 31;
            int row = row0 + r;
            Xs[r][c] = (row < NN) ? X[(size_t)row * FIN + k0 + c] : 0.f;
        }
        #pragma unroll
        for (int t = tid; t < 1024; t += 256) {    // 32x128 floats as float4
            int r = t >> 5, c = t & 31;
            reinterpret_cast<float4*>(&Ws[r][0])[c] =
                reinterpret_cast<const float4*>(&W[(size_t)(k0 + r) * FHID])[c];
        }
        __syncthreads();
        #pragma unroll
        for (int kk = 0; kk < 32; kk++) {
            float4 w = reinterpret_cast<float4*>(&Ws[kk][0])[tx];
            #pragma unroll
            for (int r = 0; r < 8; r++) {
                float xv = Xs[ty * 8 + r][kk];
                acc[r].x += xv * w.x; acc[r].y += xv * w.y;
                acc[r].z += xv * w.z; acc[r].w += xv * w.w;
            }
        }
        __syncthreads();
    }
    #pragma unroll
    for (int r = 0; r < 8; r++) {
        int row = row0 + ty * 8 + r;
        if (row < NN) {
            float s = g_dinv[row];
            float4 v = acc[r];
            v.x *= s; v.y *= s; v.z *= s; v.w *= s;
            reinterpret_cast<float4*>(&g_h1[(size_t)row * FHID])[tx] = v;
        }
    }
}

// ---------------- AGG 1: g_h2[i] = relu(dinv[i]*(sum_nb g_h1 + g_h1[i]) + b1) ----------------
__global__ void __launch_bounds__(256) k_agg1(const float* __restrict__ b1) {
    int gw   = (blockIdx.x * 256 + threadIdx.x) >> 5;   // node = warp id
    int lane = threadIdx.x & 31;
    if (gw >= NN) return;
    const float4* h = reinterpret_cast<const float4*>(g_h1);
    float4 acc = h[(size_t)gw * 32 + lane];             // self-loop term
    int s0 = g_rowptr[gw], s1 = g_rowptr[gw + 1];
    for (int j = s0; j < s1; j++) {
        int s = g_col[j];
        float4 v = h[(size_t)s * 32 + lane];
        acc.x += v.x; acc.y += v.y; acc.z += v.z; acc.w += v.w;
    }
    float dv = g_dinv[gw];
    float4 bb = reinterpret_cast<const float4*>(b1)[lane];
    float4 z;
    z.x = fmaxf(acc.x * dv + bb.x, 0.f);
    z.y = fmaxf(acc.y * dv + bb.y, 0.f);
    z.z = fmaxf(acc.z * dv + bb.z, 0.f);
    z.w = fmaxf(acc.w * dv + bb.w, 0.f);
    reinterpret_cast<float4*>(g_h2)[(size_t)gw * 32 + lane] = z;
}

// ---------------- GEMM 2: g_h2p[i] = dinv[i] * (g_h2 @ W2)[i]  (128x64) ----------------
__global__ void __launch_bounds__(256) k_gemm2(const float* __restrict__ W) {
    __shared__ float Xs[64][33];
    __shared__ float Ws[32][64];
    int tid = threadIdx.x;
    int tx = tid & 15;               // 0..15 -> 4 cols (float4), 64 cols total
    int ty = tid >> 4;               // 0..15 -> 4 rows
    int row0 = blockIdx.x * 64;
    float4 acc[4];
    #pragma unroll
    for (int r = 0; r < 4; r++) acc[r] = make_float4(0.f, 0.f, 0.f, 0.f);

    for (int k0 = 0; k0 < FHID; k0 += 32) {
        #pragma unroll
        for (int t = tid; t < 64 * 32; t += 256) {
            int r = t >> 5, c = t & 31;
            int row = row0 + r;
            Xs[r][c] = (row < NN) ? g_h2[(size_t)row * FHID + k0 + c] : 0.f;
        }
        #pragma unroll
        for (int t = tid; t < 512; t += 256) {     // 32x64 floats as float4
            int r = t >> 4, c = t & 15;
            reinterpret_cast<float4*>(&Ws[r][0])[c] =
                reinterpret_cast<const float4*>(&W[(size_t)(k0 + r) * FOUT])[c];
        }
        __syncthreads();
        #pragma unroll
        for (int kk = 0; kk < 32; kk++) {
            float4 w = reinterpret_cast<float4*>(&Ws[kk][0])[tx];
            #pragma unroll
            for (int r = 0; r < 4; r++) {
                float xv = Xs[ty * 4 + r][kk];
                acc[r].x += xv * w.x; acc[r].y += xv * w.y;
                acc[r].z += xv * w.z; acc[r].w += xv * w.w;
            }
        }
        __syncthreads();
    }
    #pragma unroll
    for (int r = 0; r < 4; r++) {
        int row = row0 + ty * 4 + r;
        if (row < NN) {
            float s = g_dinv[row];
            float4 v = acc[r];
            v.x *= s; v.y *= s; v.z *= s; v.w *= s;
            reinterpret_cast<float4*>(&g_h2p[(size_t)row * FOUT])[tx] = v;
        }
    }
}

// ---------------- AGG 2: out[i] = dinv[i]*(sum_nb g_h2p + g_h2p[i]) + b2 ----------------
__global__ void __launch_bounds__(256) k_agg2(const float* __restrict__ b2,
                                              float* __restrict__ out) {
    int gw   = (blockIdx.x * 256 + threadIdx.x) >> 5;
    int lane = threadIdx.x & 31;
    if (gw >= NN) return;
    const float2* h = reinterpret_cast<const float2*>(g_h2p);
    float2 acc = h[(size_t)gw * 32 + lane];             // self-loop term
    int s0 = g_rowptr[gw], s1 = g_rowptr[gw + 1];
    for (int j = s0; j < s1; j++) {
        int s = g_col[j];
        float2 v = h[(size_t)s * 32 + lane];
        acc.x += v.x; acc.y += v.y;
    }
    float dv = g_dinv[gw];
    float2 bb = reinterpret_cast<const float2*>(b2)[lane];
    float2 z;
    z.x = acc.x * dv + bb.x;
    z.y = acc.y * dv + bb.y;
    reinterpret_cast<float2*>(out)[(size_t)gw * 32 + lane] = z;
}

// ---------------- launch ----------------
extern "C" void kernel_launch(void* const* d_in, const int* in_sizes, int n_in,
                              void* d_out, int out_size) {
    const float* x  = (const float*)d_in[0];
    const int*   ei = (const int*)d_in[1];
    const float* W1 = (const float*)d_in[2];
    const float* b1 = (const float*)d_in[3];
    const float* W2 = (const float*)d_in[4];
    const float* b2 = (const float*)d_in[5];
    float* out = (float*)d_out;

    k_init <<<(NN + 255) / 256, 256>>>();
    k_count<<<(NE + 255) / 256, 256>>>(ei);
    k_scan <<<1, 1024>>>();
    k_fill <<<(NE + 255) / 256, 256>>>(ei);
    k_gemm1<<<(NN + 63) / 64, dim3(32, 8)>>>(x, W1);
    k_agg1 <<<(NN * 32 + 255) / 256, 256>>>(b1);
    k_gemm2<<<(NN + 63) / 64, 256>>>(W2);
    k_agg2 <<<(NN * 32 + 255) / 256, 256>>>(b2, out);
}